// round 10
// baseline (speedup 1.0000x reference)
#include <cuda_runtime.h>
#include <cuda_bf16.h>
#include <math.h>
#include <stdint.h>

namespace {
constexpr int C_ = 128;
constexpr int B_ = 8;
constexpr int T_ = 128;
constexpr int F_ = 512;
constexpr int K_ = 64;
constexpr int NL = T_ * K_;   // 8192
constexpr int NS = T_ * F_;   // 65536
}

// ---------------- scratch (device globals; no allocation allowed) ----------------
__device__ float g_lat_h[(size_t)B_ * C_ * NL];
__device__ float g_kbuf [(size_t)B_ * C_ * NL];
__device__ float g_vbuf [(size_t)B_ * C_ * NL];
__device__ float g_u  [(size_t)B_ * C_ * NS];
__device__ float g_qh [(size_t)B_ * C_ * NS];
__device__ float g_qb [(size_t)B_ * C_ * NS];
__device__ float g_att[(size_t)B_ * C_ * NS];
__device__ __align__(16) __nv_bfloat16 g_whi[11 * 16384];
__device__ __align__(16) __nv_bfloat16 g_wlo[11 * 16384];

namespace {
// weight offsets in g_whi/g_wlo (elements)
constexpr int WO_LP = 0, WO_QMI = 16384, WO_QMO = 49152, WO_Q = 65536,
              WO_K = 81920, WO_V = 98304, WO_O = 114688, WO_FFI = 131072, WO_FFO = 163840;

// A tile pitch 72 bf16 (144B): rows rotate 16B mod 128B -> ldmatrix conflict-free
constexpr int PA = 72;
// B tile pitch 136 bf16 (272B): same property
constexpr int PN = 136;

// SMEM layout (bytes) — k-chunked (k=64), single-buffered, 2 CTAs/SM
constexpr int OFF_AH   = 0;          // 18432  A hi [128][PA]
constexpr int OFF_AL   = 18432;      // 18432  A lo
constexpr int OFF_BH   = 36864;      // 17408  B hi [64][PN]
constexpr int OFF_BL   = 54272;      // 17408  B lo
constexpr int OFF_PART = 71680;      // 4096   8 warps x 128 col partials
constexpr int OFF_INV  = 75776;      // 512    inv[128]
constexpr int SMEM_G   = 76288;
}

__device__ __forceinline__ uint32_t smem_u32(const void* p) {
    uint32_t a;
    asm("{ .reg .u64 t; cvta.to.shared.u64 t, %1; cvt.u32.u64 %0, t; }" : "=r"(a) : "l"(p));
    return a;
}

#define LDSM4(r, addr) \
    asm volatile("ldmatrix.sync.aligned.m8n8.x4.shared.b16 {%0,%1,%2,%3}, [%4];" \
        : "=r"((r)[0]), "=r"((r)[1]), "=r"((r)[2]), "=r"((r)[3]) : "r"(addr))
#define LDSM4T(r, addr) \
    asm volatile("ldmatrix.sync.aligned.m8n8.x4.trans.shared.b16 {%0,%1,%2,%3}, [%4];" \
        : "=r"((r)[0]), "=r"((r)[1]), "=r"((r)[2]), "=r"((r)[3]) : "r"(addr))

__device__ __forceinline__ void mma16816(float* d, const uint32_t* a, uint32_t b0, uint32_t b1) {
    asm volatile("mma.sync.aligned.m16n8k16.row.col.f32.bf16.bf16.f32 "
        "{%0,%1,%2,%3},{%4,%5,%6,%7},{%8,%9},{%0,%1,%2,%3};"
        : "+f"(d[0]), "+f"(d[1]), "+f"(d[2]), "+f"(d[3])
        : "r"(a[0]), "r"(a[1]), "r"(a[2]), "r"(a[3]), "r"(b0), "r"(b1));
}

// ---------------- weight prep: all 9 weights in one launch ----------------
__global__ void wprep_all(
    const float* lp_w, const float* lp_g,
    const float* qmi_w, const float* qmi_g,
    const float* qmo_w, const float* q_w, const float* k_w, const float* v_w,
    const float* o_w,
    const float* ffi_w, const float* ffi_g,
    const float* ffo_w,
    __nv_bfloat16* __restrict__ hi, __nv_bfloat16* __restrict__ lo)
{
    const int id = blockIdx.y;
    const float* W; const float* gamma = nullptr; int off, n;
    switch (id) {
        case 0: W = lp_w;  gamma = lp_g;  off = WO_LP;  n = 16384; break;
        case 1: W = qmi_w; gamma = qmi_g; off = WO_QMI; n = 32768; break;
        case 2: W = qmo_w;                off = WO_QMO; n = 16384; break;
        case 3: W = q_w;                  off = WO_Q;   n = 16384; break;
        case 4: W = k_w;                  off = WO_K;   n = 16384; break;
        case 5: W = v_w;                  off = WO_V;   n = 16384; break;
        case 6: W = o_w;                  off = WO_O;   n = 16384; break;
        case 7: W = ffi_w; gamma = ffi_g; off = WO_FFI; n = 32768; break;
        default:W = ffo_w;                off = WO_FFO; n = 16384; break;
    }
    int i = blockIdx.x * 256 + threadIdx.x;
    if (i >= n) return;
    float v = W[i];
    if (gamma) v *= gamma[i & (C_ - 1)];
    __nv_bfloat16 h = __float2bfloat16(v);
    hi[off + i] = h;
    lo[off + i] = __float2bfloat16(v - __bfloat162float(h));
}

__device__ __forceinline__ void cvt4store(float4 v, __nv_bfloat16* ph, __nv_bfloat16* pl) {
    __align__(8) __nv_bfloat16 h[4], l[4];
    float f[4] = {v.x, v.y, v.z, v.w};
#pragma unroll
    for (int j = 0; j < 4; j++) {
        __nv_bfloat16 hb = __float2bfloat16(f[j]);
        h[j] = hb;
        l[j] = __float2bfloat16(f[j] - __bfloat162float(hb));
    }
    *(uint2*)ph = *(uint2*)h;
    *(uint2*)pl = *(uint2*)l;
}

// ---------------- HMMA GEMM, tile M=128 N=128, K=128 in 2 chunks of 64 ----------------
// EPI: 0 none, 1 silu, 2 swiglu (a/g rows interleaved), 3 +skip*sscale, 4 accumulate into Y
// RMS: rmsnorm folded as per-column scale applied in the EPILOGUE (W@(x*inv) = (W@x)*inv)
template <int EPI, bool RMS>
__global__ void __launch_bounds__(256, 2) gemm_mma(
    const __nv_bfloat16* __restrict__ Whi, const __nv_bfloat16* __restrict__ Wlo,
    const float* __restrict__ bias, const float* __restrict__ X,
    const float* __restrict__ skip, const float* __restrict__ sscale,
    float* __restrict__ Y, int N)
{
    extern __shared__ __align__(16) char sm[];
    const int tid = threadIdx.x, wid = tid >> 5, lane = tid & 31;
    const int b = blockIdx.z, n0 = blockIdx.x * 128;
    __nv_bfloat16* Ah = (__nv_bfloat16*)(sm + OFF_AH);
    __nv_bfloat16* Al = (__nv_bfloat16*)(sm + OFF_AL);
    __nv_bfloat16* Bh = (__nv_bfloat16*)(sm + OFF_BH);
    __nv_bfloat16* Bl = (__nv_bfloat16*)(sm + OFF_BL);
    float* inv = (float*)(sm + OFF_INV);

    const float* Xb = X + (size_t)b * C_ * N + n0;

    // ---- RMS sumsq pre-pass: row-parallel, per-column partials -> inv[n]
    if (RMS) {
        float* part = (float*)(sm + OFF_PART);
        float sq0 = 0.f, sq1 = 0.f, sq2 = 0.f, sq3 = 0.f;
#pragma unroll 4
        for (int c = wid; c < C_; c += 8) {
            float4 v = *(const float4*)(Xb + (size_t)c * N + lane * 4);
            sq0 = fmaf(v.x, v.x, sq0); sq1 = fmaf(v.y, v.y, sq1);
            sq2 = fmaf(v.z, v.z, sq2); sq3 = fmaf(v.w, v.w, sq3);
        }
        part[wid * 128 + lane * 4 + 0] = sq0;
        part[wid * 128 + lane * 4 + 1] = sq1;
        part[wid * 128 + lane * 4 + 2] = sq2;
        part[wid * 128 + lane * 4 + 3] = sq3;
        __syncthreads();
        if (tid < 128) {
            float s = 0.f;
#pragma unroll
            for (int w = 0; w < 8; w++) s += part[w * 128 + tid];
            inv[tid] = rsqrtf(s * (1.0f / 128.0f) + 1e-6f);
        }
        // inv consumed only in epilogue; chunk syncs below order it
    }

    const int wm = (wid & 3) * 32, wn = (wid >> 2) * 64;
    float acc[2][8][4];
#pragma unroll
    for (int mf = 0; mf < 2; mf++)
#pragma unroll
        for (int nb = 0; nb < 8; nb++)
#pragma unroll
            for (int j = 0; j < 4; j++) acc[mf][nb][j] = 0.f;

    const uint32_t sb = smem_u32(sm);
    const uint32_t aOff = ((wm + (lane & 15)) * PA + (lane >> 4) * 8) * 2;
    const uint32_t bOff = ((lane & 15) * PN + wn + (lane >> 4) * 8) * 2;

    // A row selection (weight row for mma row r)
    const int ar = tid >> 1;
    int wrow;
    if (EPI == 2) {
        int ch = blockIdx.y * 64 + (ar >> 1);
        wrow = (ar & 1) ? (C_ + ch) : ch;     // even mma row = a, odd = g
    } else {
        wrow = ar;
    }

#pragma unroll
    for (int kc = 0; kc < 2; kc++) {
        // ---- load A chunk: rows 128 x cols kc*64..+63, hi/lo
        {
            const int h = (tid & 1) * 32;     // 32-col half within chunk
            const uint4* sh = (const uint4*)(Whi + (size_t)wrow * C_ + kc * 64 + h);
            const uint4* sl = (const uint4*)(Wlo + (size_t)wrow * C_ + kc * 64 + h);
            uint4* dh = (uint4*)(Ah + ar * PA + h);
            uint4* dl = (uint4*)(Al + ar * PA + h);
#pragma unroll
            for (int i = 0; i < 4; i++) { dh[i] = sh[i]; dl[i] = sl[i]; }
        }
        // ---- load + convert B chunk: k rows kc*64..+63 x 128 cols
        {
            const int cl = tid >> 2;                 // local k row 0..63
            const int colg = (tid & 3) * 32;
            const float* src = Xb + (size_t)(kc * 64 + cl) * N + colg;
#pragma unroll
            for (int i = 0; i < 8; i++) {
                float4 v = *(const float4*)(src + i * 4);
                cvt4store(v, Bh + cl * PN + colg + i * 4, Bl + cl * PN + colg + i * 4);
            }
        }
        __syncthreads();

        // ---- mainloop: 4 k16-steps; shared LDSM across the 3 split passes
#pragma unroll
        for (int ks = 0; ks < 4; ks++) {
            uint32_t aH0[4], aH1[4], aL0[4], aL1[4];
            LDSM4(aH0, sb + OFF_AH + aOff + ks * 32);
            LDSM4(aH1, sb + OFF_AH + aOff + 16 * PA * 2 + ks * 32);
            LDSM4(aL0, sb + OFF_AL + aOff + ks * 32);
            LDSM4(aL1, sb + OFF_AL + aOff + 16 * PA * 2 + ks * 32);
#pragma unroll
            for (int n2 = 0; n2 < 4; n2++) {
                uint32_t bh[4], bl[4];
                LDSM4T(bh, sb + OFF_BH + bOff + ks * 16 * PN * 2 + n2 * 32);
                LDSM4T(bl, sb + OFF_BL + bOff + ks * 16 * PN * 2 + n2 * 32);
                // hi*hi
                mma16816(acc[0][n2 * 2 + 0], aH0, bh[0], bh[1]);
                mma16816(acc[0][n2 * 2 + 1], aH0, bh[2], bh[3]);
                mma16816(acc[1][n2 * 2 + 0], aH1, bh[0], bh[1]);
                mma16816(acc[1][n2 * 2 + 1], aH1, bh[2], bh[3]);
                // hi*lo
                mma16816(acc[0][n2 * 2 + 0], aH0, bl[0], bl[1]);
                mma16816(acc[0][n2 * 2 + 1], aH0, bl[2], bl[3]);
                mma16816(acc[1][n2 * 2 + 0], aH1, bl[0], bl[1]);
                mma16816(acc[1][n2 * 2 + 1], aH1, bl[2], bl[3]);
                // lo*hi
                mma16816(acc[0][n2 * 2 + 0], aL0, bh[0], bh[1]);
                mma16816(acc[0][n2 * 2 + 1], aL0, bh[2], bh[3]);
                mma16816(acc[1][n2 * 2 + 0], aL1, bh[0], bh[1]);
                mma16816(acc[1][n2 * 2 + 1], aL1, bh[2], bh[3]);
            }
        }
        __syncthreads();   // before overwriting buffers with next chunk
    }

    // ---- epilogue. frag map: d0,d1 -> row g=lane>>2, cols q*2,q*2+1; d2,d3 -> row g+8
    const int g = lane >> 2, q = lane & 3;
    if (EPI == 2) {
        const int chBase = blockIdx.y * 64 + (wm >> 1);
#pragma unroll
        for (int mf = 0; mf < 2; mf++) {
            const int ch = chBase + mf * 8 + (g >> 1);   // valid when g even
            float ba0 = bias[ch], bg0 = bias[C_ + ch];
            float ba1 = bias[ch + 4], bg1 = bias[C_ + ch + 4];
#pragma unroll
            for (int nb = 0; nb < 8; nb++) {
                float* d = acc[mf][nb];
                float d0 = d[0], d1 = d[1], d2 = d[2], d3 = d[3];
                if (RMS) {
                    float2 iv = *(const float2*)(inv + wn + nb * 8 + q * 2);
                    d0 *= iv.x; d1 *= iv.y; d2 *= iv.x; d3 *= iv.y;
                }
                float gt0 = __shfl_down_sync(0xffffffffu, d0, 4);
                float gt1 = __shfl_down_sync(0xffffffffu, d1, 4);
                float gt2 = __shfl_down_sync(0xffffffffu, d2, 4);
                float gt3 = __shfl_down_sync(0xffffffffu, d3, 4);
                if (!(g & 1)) {
                    float a0 = d0 + ba0, a1 = d1 + ba0;
                    float g0 = gt0 + bg0, g1 = gt1 + bg0;
                    float a2 = d2 + ba1, a3 = d3 + ba1;
                    float g2 = gt2 + bg1, g3 = gt3 + bg1;
                    float o0 = a0 * (g0 / (1.f + __expf(-g0)));
                    float o1 = a1 * (g1 / (1.f + __expf(-g1)));
                    float o2 = a2 * (g2 / (1.f + __expf(-g2)));
                    float o3 = a3 * (g3 / (1.f + __expf(-g3)));
                    int col = n0 + wn + nb * 8 + q * 2;
                    *(float2*)(Y + ((size_t)b * C_ + ch) * N + col) = make_float2(o0, o1);
                    *(float2*)(Y + ((size_t)b * C_ + ch + 4) * N + col) = make_float2(o2, o3);
                }
            }
        }
    } else {
        const float sv = (EPI == 3) ? *sscale : 0.f;
#pragma unroll
        for (int mf = 0; mf < 2; mf++) {
            const int r0 = wm + mf * 16 + g;
            const float bo0 = bias[r0], bo1 = bias[r0 + 8];
            float* y0 = Y + ((size_t)b * C_ + r0) * N + n0 + wn;
            float* y1 = Y + ((size_t)b * C_ + r0 + 8) * N + n0 + wn;
            const float* s0 = (EPI == 3) ? (skip + ((size_t)b * C_ + r0) * N + n0 + wn) : nullptr;
            const float* s1 = (EPI == 3) ? (skip + ((size_t)b * C_ + r0 + 8) * N + n0 + wn) : nullptr;
#pragma unroll
            for (int nb = 0; nb < 8; nb++) {
                float* d = acc[mf][nb];
                int col = nb * 8 + q * 2;
                float d0 = d[0], d1 = d[1], d2 = d[2], d3 = d[3];
                if (RMS) {
                    float2 iv = *(const float2*)(inv + wn + col);
                    d0 *= iv.x; d1 *= iv.y; d2 *= iv.x; d3 *= iv.y;
                }
                float o0 = d0 + bo0, o1 = d1 + bo0;
                float o2 = d2 + bo1, o3 = d3 + bo1;
                if (EPI == 1) {
                    o0 = o0 / (1.f + __expf(-o0));
                    o1 = o1 / (1.f + __expf(-o1));
                    o2 = o2 / (1.f + __expf(-o2));
                    o3 = o3 / (1.f + __expf(-o3));
                }
                if (EPI == 3) {
                    float2 k0 = *(const float2*)(s0 + col);
                    float2 k1 = *(const float2*)(s1 + col);
                    o0 += k0.x * sv; o1 += k0.y * sv;
                    o2 += k1.x * sv; o3 += k1.y * sv;
                }
                if (EPI == 4) {
                    float2 k0 = *(const float2*)(y0 + col);
                    float2 k1 = *(const float2*)(y1 + col);
                    o0 += k0.x; o1 += k0.y;
                    o2 += k1.x; o3 += k1.y;
                }
                *(float2*)(y0 + col) = make_float2(o0, o1);
                *(float2*)(y1 + col) = make_float2(o2, o3);
            }
        }
    }
}

// ---------------- packed fp32x2 helpers (SIMT attention) ----------------
typedef unsigned long long u64;
__device__ __forceinline__ u64 pk2(float x, float y) {
    u64 r; asm("mov.b64 %0,{%1,%2};" : "=l"(r) : "f"(x), "f"(y)); return r;
}
__device__ __forceinline__ void up2(u64 v, float& x, float& y) {
    asm("mov.b64 {%0,%1},%2;" : "=f"(x), "=f"(y) : "l"(v));
}
__device__ __forceinline__ void fma2(u64& c, u64 a, u64 b) {
    asm("fma.rn.f32x2 %0,%1,%2,%0;" : "+l"(c) : "l"(a), "l"(b));
}

// ---------------- per-frame cross attention: one block per (b,t) ----------------
__global__ void __launch_bounds__(256) attn_kernel(
    const float* __restrict__ Q, const float* __restrict__ Kp, const float* __restrict__ Vp,
    const float* __restrict__ basis, const float* __restrict__ p_ss, const float* __restrict__ p_ps,
    float* __restrict__ Att)
{
    extern __shared__ float smf[];
    float* ks  = smf;                  // [128][64]
    float* vst = ks + 128 * 64;        // [64][132]
    float* qs  = vst + 64 * 132;       // [128][64]
    float* pst = qs + 128 * 64;        // [64][68]
    const int t = blockIdx.x, b = blockIdx.y;
    const int tid = threadIdx.x;
    const int ty = tid >> 4, tx = tid & 15;
    const float ss = *p_ss, prs = *p_ps;

    for (int idx = tid; idx < C_ * K_; idx += 256) {
        int c = idx >> 6, kk = idx & 63;
        size_t g = (((size_t)b * C_ + c) * T_ + t) * K_ + kk;
        ks[c * 64 + kk]   = Kp[g];
        vst[kk * 132 + c] = Vp[g];
    }
    __syncthreads();

    for (int f0 = 0; f0 < F_; f0 += 64) {
        for (int idx = tid; idx < C_ * 64; idx += 256) {
            int c = idx >> 6, fl = idx & 63;
            qs[c * 64 + fl] = Q[(((size_t)b * C_ + c) * T_ + t) * F_ + f0 + fl];
        }
        __syncthreads();

        u64 acc[4][2];
#pragma unroll
        for (int r = 0; r < 4; r++) { acc[r][0] = 0ull; acc[r][1] = 0ull; }
#pragma unroll 8
        for (int c = 0; c < C_; c++) {
            float4 av = *(const float4*)&qs[c * 64 + ty * 4];
            float4 bv = *(const float4*)&ks[c * 64 + tx * 4];
            u64 b0 = pk2(bv.x, bv.y), b1 = pk2(bv.z, bv.w);
            u64 a0 = pk2(av.x, av.x); fma2(acc[0][0], a0, b0); fma2(acc[0][1], a0, b1);
            u64 a1 = pk2(av.y, av.y); fma2(acc[1][0], a1, b0); fma2(acc[1][1], a1, b1);
            u64 a2 = pk2(av.z, av.z); fma2(acc[2][0], a2, b0); fma2(acc[2][1], a2, b1);
            u64 a3 = pk2(av.w, av.w); fma2(acc[3][0], a3, b0); fma2(acc[3][1], a3, b1);
        }

#pragma unroll
        for (int r = 0; r < 4; r++) {
            float s0, s1, s2, s3;
            up2(acc[r][0], s0, s1);
            up2(acc[r][1], s2, s3);
            int f = f0 + ty * 4 + r;
            s0 = fmaf(s0, ss, basis[(tx * 4 + 0) * F_ + f] * prs);
            s1 = fmaf(s1, ss, basis[(tx * 4 + 1) * F_ + f] * prs);
            s2 = fmaf(s2, ss, basis[(tx * 4 + 2) * F_ + f] * prs);
            s3 = fmaf(s3, ss, basis[(tx * 4 + 3) * F_ + f] * prs);
            float m = fmaxf(fmaxf(s0, s1), fmaxf(s2, s3));
            m = fmaxf(m, __shfl_xor_sync(0xffffffffu, m, 1));
            m = fmaxf(m, __shfl_xor_sync(0xffffffffu, m, 2));
            m = fmaxf(m, __shfl_xor_sync(0xffffffffu, m, 4));
            m = fmaxf(m, __shfl_xor_sync(0xffffffffu, m, 8));
            float e0 = __expf(s0 - m), e1 = __expf(s1 - m);
            float e2 = __expf(s2 - m), e3 = __expf(s3 - m);
            float sum = (e0 + e1) + (e2 + e3);
            sum += __shfl_xor_sync(0xffffffffu, sum, 1);
            sum += __shfl_xor_sync(0xffffffffu, sum, 2);
            sum += __shfl_xor_sync(0xffffffffu, sum, 4);
            sum += __shfl_xor_sync(0xffffffffu, sum, 8);
            float rs = 1.f / sum;
            int fl = ty * 4 + r;
            pst[(tx * 4 + 0) * 68 + fl] = e0 * rs;
            pst[(tx * 4 + 1) * 68 + fl] = e1 * rs;
            pst[(tx * 4 + 2) * 68 + fl] = e2 * rs;
            pst[(tx * 4 + 3) * 68 + fl] = e3 * rs;
        }
        __syncthreads();

        u64 acc2[8][2];
#pragma unroll
        for (int r = 0; r < 8; r++) { acc2[r][0] = 0ull; acc2[r][1] = 0ull; }
#pragma unroll 4
        for (int kk = 0; kk < K_; kk++) {
            float4 bv = *(const float4*)&pst[kk * 68 + tx * 4];
            u64 b0 = pk2(bv.x, bv.y), b1 = pk2(bv.z, bv.w);
            const float* vr = &vst[kk * 132 + ty * 8];
#pragma unroll
            for (int r = 0; r < 8; r++) {
                u64 ar = pk2(vr[r], vr[r]);
                fma2(acc2[r][0], ar, b0);
                fma2(acc2[r][1], ar, b1);
            }
        }
#pragma unroll
        for (int r = 0; r < 8; r++) {
            int c = ty * 8 + r;
            float v0, v1, v2, v3;
            up2(acc2[r][0], v0, v1);
            up2(acc2[r][1], v2, v3);
            *(float4*)&Att[(((size_t)b * C_ + c) * T_ + t) * F_ + f0 + tx * 4] =
                make_float4(v0, v1, v2, v3);
        }
        __syncthreads();
    }
}

// ---------------- launch ----------------
extern "C" void kernel_launch(void* const* d_in, const int* in_sizes, int n_in,
                              void* d_out, int out_size)
{
    const float* latent     = (const float*)d_in[0];
    const float* side       = (const float*)d_in[1];
    const float* basis      = (const float*)d_in[2];
    const float* lp_gamma   = (const float*)d_in[3];
    const float* lp_w       = (const float*)d_in[4];
    const float* lp_b       = (const float*)d_in[5];
    const float* qn_gamma   = (const float*)d_in[6];
    const float* qmlp_in_w  = (const float*)d_in[7];
    const float* qmlp_in_b  = (const float*)d_in[8];
    const float* qmlp_out_w = (const float*)d_in[9];
    const float* qmlp_out_b = (const float*)d_in[10];
    const float* q_w        = (const float*)d_in[11];
    const float* q_b        = (const float*)d_in[12];
    const float* k_w        = (const float*)d_in[13];
    const float* k_b        = (const float*)d_in[14];
    const float* v_w        = (const float*)d_in[15];
    const float* v_b        = (const float*)d_in[16];
    const float* o_w        = (const float*)d_in[17];
    const float* o_b        = (const float*)d_in[18];
    const float* ffn_gamma  = (const float*)d_in[19];
    const float* ffn_in_w   = (const float*)d_in[20];
    const float* ffn_in_b   = (const float*)d_in[21];
    const float* ffn_out_w  = (const float*)d_in[22];
    const float* ffn_out_b  = (const float*)d_in[23];
    const float* score_scale= (const float*)d_in[24];
    const float* prior_scale= (const float*)d_in[25];
    const float* qss        = (const float*)d_in[26];
    float* out = (float*)d_out;

    void* p;
    cudaGetSymbolAddress(&p, g_lat_h); float* lat_h = (float*)p;
    cudaGetSymbolAddress(&p, g_kbuf);  float* kb    = (float*)p;
    cudaGetSymbolAddress(&p, g_vbuf);  float* vb    = (float*)p;
    cudaGetSymbolAddress(&p, g_u);     float* u     = (float*)p;
    cudaGetSymbolAddress(&p, g_qh);    float* qh    = (float*)p;
    cudaGetSymbolAddress(&p, g_qb);    float* qb    = (float*)p;
    cudaGetSymbolAddress(&p, g_att);   float* att   = (float*)p;
    cudaGetSymbolAddress(&p, g_whi);   __nv_bfloat16* whi = (__nv_bfloat16*)p;
    cudaGetSymbolAddress(&p, g_wlo);   __nv_bfloat16* wlo = (__nv_bfloat16*)p;

    // ---- weight prep (bf16 hi/lo, gamma folded) — single launch
    wprep_all<<<dim3(128, 9), 256>>>(lp_w, lp_gamma, qmlp_in_w, qn_gamma,
                                     qmlp_out_w, q_w, k_w, v_w, o_w,
                                     ffn_in_w, ffn_gamma, ffn_out_w, whi, wlo);

    cudaFuncSetAttribute(gemm_mma<0, false>, cudaFuncAttributeMaxDynamicSharedMemorySize, SMEM_G);
    cudaFuncSetAttribute(gemm_mma<1, true>,  cudaFuncAttributeMaxDynamicSharedMemorySize, SMEM_G);
    cudaFuncSetAttribute(gemm_mma<2, true>,  cudaFuncAttributeMaxDynamicSharedMemorySize, SMEM_G);
    cudaFuncSetAttribute(gemm_mma<3, false>, cudaFuncAttributeMaxDynamicSharedMemorySize, SMEM_G);
    cudaFuncSetAttribute(gemm_mma<4, false>, cudaFuncAttributeMaxDynamicSharedMemorySize, SMEM_G);

    // ---- latent path: latent_h = silu(lp(rmsnorm(latent))); k, v projections
    gemm_mma<1, true><<<dim3(NL / 128, 1, B_), 256, SMEM_G>>>(
        whi + WO_LP, wlo + WO_LP, lp_b, latent, nullptr, nullptr, lat_h, NL);
    gemm_mma<0, false><<<dim3(NL / 128, 1, B_), 256, SMEM_G>>>(
        whi + WO_K, wlo + WO_K, k_b, lat_h, nullptr, nullptr, kb, NL);
    gemm_mma<0, false><<<dim3(NL / 128, 1, B_), 256, SMEM_G>>>(
        whi + WO_V, wlo + WO_V, v_b, lat_h, nullptr, nullptr, vb, NL);

    // ---- side path: u = glu(qmlp_in(rmsnorm(side))); qh = qmlp_out(u); qb = q(qh)
    gemm_mma<2, true><<<dim3(NS / 128, 2, B_), 256, SMEM_G>>>(
        whi + WO_QMI, wlo + WO_QMI, qmlp_in_b, side, nullptr, nullptr, u, NS);
    gemm_mma<0, false><<<dim3(NS / 128, 1, B_), 256, SMEM_G>>>(
        whi + WO_QMO, wlo + WO_QMO, qmlp_out_b, u, nullptr, nullptr, qh, NS);
    gemm_mma<0, false><<<dim3(NS / 128, 1, B_), 256, SMEM_G>>>(
        whi + WO_Q, wlo + WO_Q, q_b, qh, nullptr, nullptr, qb, NS);

    // ---- attention (per-frame) -> attended
    constexpr int ATTN_SMEM = (128 * 64 + 64 * 132 + 128 * 64 + 64 * 68) * 4;  // 116736
    cudaFuncSetAttribute(attn_kernel, cudaFuncAttributeMaxDynamicSharedMemorySize, ATTN_SMEM);
    attn_kernel<<<dim3(T_, B_), 256, ATTN_SMEM>>>(qb, kb, vb, basis, score_scale, prior_scale, att);

    // ---- hidden = o(attended) + o_b + qh * qss
    gemm_mma<3, false><<<dim3(NS / 128, 1, B_), 256, SMEM_G>>>(
        whi + WO_O, wlo + WO_O, o_b, att, qh, qss, out, NS);

    // ---- ffn: hidden += ffn_out(glu(ffn_in(rmsnorm(hidden))))
    gemm_mma<2, true><<<dim3(NS / 128, 2, B_), 256, SMEM_G>>>(
        whi + WO_FFI, wlo + WO_FFI, ffn_in_b, out, nullptr, nullptr, u, NS);
    gemm_mma<4, false><<<dim3(NS / 128, 1, B_), 256, SMEM_G>>>(
        whi + WO_FFO, wlo + WO_FFO, ffn_out_b, u, nullptr, nullptr, out, NS);
}

// round 12
// speedup vs baseline: 1.7291x; 1.7291x over previous
#include <cuda_runtime.h>
#include <cuda_bf16.h>
#include <math.h>
#include <stdint.h>

namespace {
constexpr int C_ = 128;
constexpr int B_ = 8;
constexpr int T_ = 128;
constexpr int F_ = 512;
constexpr int K_ = 64;
constexpr int NL = T_ * K_;   // 8192
constexpr int NS = T_ * F_;   // 65536
}

// ---------------- scratch (device globals; no allocation allowed) ----------------
__device__ float g_lat_h[(size_t)B_ * C_ * NL];
__device__ float g_kqov [(size_t)2 * B_ * C_ * NL];   // [Kq ; OV]
__device__ float g_u  [(size_t)B_ * C_ * NS];
__device__ float g_qh [(size_t)B_ * C_ * NS];
__device__ float g_small[512];                        // b_kq[128], b_ov[128], w_kqb[128], b_kqb
__device__ __align__(16) __nv_bfloat16 g_whi[10 * 16384];
__device__ __align__(16) __nv_bfloat16 g_wlo[10 * 16384];

namespace {
// weight offsets (elements)
constexpr int WO_LP = 0, WO_QMI = 16384, WO_QMO = 49152,
              WO_FFI = 65536, WO_FFO = 98304, WO_KQ = 114688, WO_OV = 131072;

constexpr int PA = 72;    // A pitch (bf16): 144B rows rotate mod 128B -> conflict-free ldmatrix
constexpr int PN = 136;   // B pitch

constexpr int OFF_AH   = 0;
constexpr int OFF_AL   = 18432;
constexpr int OFF_BH   = 36864;
constexpr int OFF_BL   = 54272;
constexpr int OFF_PART = 71680;
constexpr int OFF_INV  = 75776;
constexpr int SMEM_G   = 76288;
}

__device__ __forceinline__ uint32_t smem_u32(const void* p) {
    uint32_t a;
    asm("{ .reg .u64 t; cvta.to.shared.u64 t, %1; cvt.u32.u64 %0, t; }" : "=r"(a) : "l"(p));
    return a;
}

#define LDSM4(r, addr) \
    asm volatile("ldmatrix.sync.aligned.m8n8.x4.shared.b16 {%0,%1,%2,%3}, [%4];" \
        : "=r"((r)[0]), "=r"((r)[1]), "=r"((r)[2]), "=r"((r)[3]) : "r"(addr))
#define LDSM4T(r, addr) \
    asm volatile("ldmatrix.sync.aligned.m8n8.x4.trans.shared.b16 {%0,%1,%2,%3}, [%4];" \
        : "=r"((r)[0]), "=r"((r)[1]), "=r"((r)[2]), "=r"((r)[3]) : "r"(addr))

__device__ __forceinline__ void mma16816(float* d, const uint32_t* a, uint32_t b0, uint32_t b1) {
    asm volatile("mma.sync.aligned.m16n8k16.row.col.f32.bf16.bf16.f32 "
        "{%0,%1,%2,%3},{%4,%5,%6,%7},{%8,%9},{%0,%1,%2,%3};"
        : "+f"(d[0]), "+f"(d[1]), "+f"(d[2]), "+f"(d[3])
        : "r"(a[0]), "r"(a[1]), "r"(a[2]), "r"(a[3]), "r"(b0), "r"(b1));
}

// ---------------- weight prep + composition, one launch ----------------
// y: 0 LP, 1 QMI, 2 QMO, 3 FFI, 4 FFO, 5 WKQ=Qw^T@Kw, 6 WOV=Ow@Vw, 7 small vectors
__global__ void wprep_all(
    const float* lp_w, const float* lp_g,
    const float* qmi_w, const float* qmi_g,
    const float* qmo_w,
    const float* ffi_w, const float* ffi_g,
    const float* ffo_w,
    const float* q_w, const float* k_w, const float* v_w, const float* o_w,
    const float* q_b, const float* k_b, const float* v_b,
    __nv_bfloat16* __restrict__ hi, __nv_bfloat16* __restrict__ lo,
    float* __restrict__ small)
{
    const int id = blockIdx.y;
    const int i = blockIdx.x * 256 + threadIdx.x;
    if (id <= 4) {
        const float* W; const float* gamma = nullptr; int off, n;
        switch (id) {
            case 0: W = lp_w;  gamma = lp_g;  off = WO_LP;  n = 16384; break;
            case 1: W = qmi_w; gamma = qmi_g; off = WO_QMI; n = 32768; break;
            case 2: W = qmo_w;                off = WO_QMO; n = 16384; break;
            case 3: W = ffi_w; gamma = ffi_g; off = WO_FFI; n = 32768; break;
            default:W = ffo_w;                off = WO_FFO; n = 16384; break;
        }
        if (i >= n) return;
        float v = W[i];
        if (gamma) v *= gamma[i & (C_ - 1)];
        __nv_bfloat16 h = __float2bfloat16(v);
        hi[off + i] = h;
        lo[off + i] = __float2bfloat16(v - __bfloat162float(h));
    } else if (id == 5) {
        if (i >= 16384) return;
        int r = i >> 7, c = i & 127;
        float s = 0.f;
#pragma unroll 8
        for (int j = 0; j < 128; j++) s = fmaf(q_w[j * 128 + r], k_w[j * 128 + c], s);
        __nv_bfloat16 h = __float2bfloat16(s);
        hi[WO_KQ + i] = h;
        lo[WO_KQ + i] = __float2bfloat16(s - __bfloat162float(h));
    } else if (id == 6) {
        if (i >= 16384) return;
        int r = i >> 7, c = i & 127;
        float s = 0.f;
#pragma unroll 8
        for (int j = 0; j < 128; j++) s = fmaf(o_w[r * 128 + j], v_w[j * 128 + c], s);
        __nv_bfloat16 h = __float2bfloat16(s);
        hi[WO_OV + i] = h;
        lo[WO_OV + i] = __float2bfloat16(s - __bfloat162float(h));
    } else {
        if (i < 128) {                       // b_kq = Qw^T @ k_b
            float s = 0.f;
            for (int j = 0; j < 128; j++) s = fmaf(q_w[j * 128 + i], k_b[j], s);
            small[i] = s;
        } else if (i < 256) {                // b_ov = Ow @ v_b
            int r = i - 128;
            float s = 0.f;
            for (int j = 0; j < 128; j++) s = fmaf(o_w[r * 128 + j], v_b[j], s);
            small[i] = s;
        } else if (i < 384) {                // w_kqb = q_b^T @ Kw
            int c = i - 256;
            float s = 0.f;
            for (int j = 0; j < 128; j++) s = fmaf(q_b[j], k_w[j * 128 + c], s);
            small[i] = s;
        } else if (i == 384) {               // b_kqb = q_b . k_b
            float s = 0.f;
            for (int j = 0; j < 128; j++) s = fmaf(q_b[j], k_b[j], s);
            small[384] = s;
        }
    }
}

__device__ __forceinline__ void cvt4store(float4 v, __nv_bfloat16* ph, __nv_bfloat16* pl) {
    __align__(8) __nv_bfloat16 h[4], l[4];
    float f[4] = {v.x, v.y, v.z, v.w};
#pragma unroll
    for (int j = 0; j < 4; j++) {
        __nv_bfloat16 hb = __float2bfloat16(f[j]);
        h[j] = hb;
        l[j] = __float2bfloat16(f[j] - __bfloat162float(hb));
    }
    *(uint2*)ph = *(uint2*)h;
    *(uint2*)pl = *(uint2*)l;
}

// ---------------- HMMA GEMM, tile M=128 N=128, K=128 in 2 chunks of 64 ----------------
// EPI: 0 none, 1 silu, 2 swiglu (a/g interleaved), 4 accumulate into Y
// RMS: rmsnorm as per-column scale in epilogue.  STK: blockIdx.y stacks weights/bias/Y.
template <int EPI, bool RMS, bool STK>
__global__ void __launch_bounds__(256, 2) gemm_mma(
    const __nv_bfloat16* __restrict__ Whi, const __nv_bfloat16* __restrict__ Wlo,
    const float* __restrict__ bias, const float* __restrict__ X,
    float* __restrict__ Y, int N, size_t ystride)
{
    extern __shared__ __align__(16) char sm[];
    const int tid = threadIdx.x, wid = tid >> 5, lane = tid & 31;
    const int b = blockIdx.z, n0 = blockIdx.x * 128;
    __nv_bfloat16* Ah = (__nv_bfloat16*)(sm + OFF_AH);
    __nv_bfloat16* Al = (__nv_bfloat16*)(sm + OFF_AL);
    __nv_bfloat16* Bh = (__nv_bfloat16*)(sm + OFF_BH);
    __nv_bfloat16* Bl = (__nv_bfloat16*)(sm + OFF_BL);
    float* inv = (float*)(sm + OFF_INV);

    if (STK) Y += blockIdx.y * ystride;
    const float* Xb = X + (size_t)b * C_ * N + n0;

    if (RMS) {
        float* part = (float*)(sm + OFF_PART);
        float sq0 = 0.f, sq1 = 0.f, sq2 = 0.f, sq3 = 0.f;
#pragma unroll 4
        for (int c = wid; c < C_; c += 8) {
            float4 v = *(const float4*)(Xb + (size_t)c * N + lane * 4);
            sq0 = fmaf(v.x, v.x, sq0); sq1 = fmaf(v.y, v.y, sq1);
            sq2 = fmaf(v.z, v.z, sq2); sq3 = fmaf(v.w, v.w, sq3);
        }
        part[wid * 128 + lane * 4 + 0] = sq0;
        part[wid * 128 + lane * 4 + 1] = sq1;
        part[wid * 128 + lane * 4 + 2] = sq2;
        part[wid * 128 + lane * 4 + 3] = sq3;
        __syncthreads();
        if (tid < 128) {
            float s = 0.f;
#pragma unroll
            for (int w = 0; w < 8; w++) s += part[w * 128 + tid];
            inv[tid] = rsqrtf(s * (1.0f / 128.0f) + 1e-6f);
        }
    }

    const int wm = (wid & 3) * 32, wn = (wid >> 2) * 64;
    float acc[2][8][4];
#pragma unroll
    for (int mf = 0; mf < 2; mf++)
#pragma unroll
        for (int nb = 0; nb < 8; nb++)
#pragma unroll
            for (int j = 0; j < 4; j++) acc[mf][nb][j] = 0.f;

    const uint32_t sb = smem_u32(sm);
    const uint32_t aOff = ((wm + (lane & 15)) * PA + (lane >> 4) * 8) * 2;
    const uint32_t bOff = ((lane & 15) * PN + wn + (lane >> 4) * 8) * 2;

    const int ar = tid >> 1;
    int wrow;
    if (EPI == 2) {
        int ch = blockIdx.y * 64 + (ar >> 1);
        wrow = (ar & 1) ? (C_ + ch) : ch;
    } else if (STK) {
        wrow = blockIdx.y * 128 + ar;
    } else {
        wrow = ar;
    }

#pragma unroll
    for (int kc = 0; kc < 2; kc++) {
        {
            const int h = (tid & 1) * 32;
            const uint4* sh = (const uint4*)(Whi + (size_t)wrow * C_ + kc * 64 + h);
            const uint4* sl = (const uint4*)(Wlo + (size_t)wrow * C_ + kc * 64 + h);
            uint4* dh = (uint4*)(Ah + ar * PA + h);
            uint4* dl = (uint4*)(Al + ar * PA + h);
#pragma unroll
            for (int i = 0; i < 4; i++) { dh[i] = sh[i]; dl[i] = sl[i]; }
        }
        {
            const int cl = tid >> 2;
            const int colg = (tid & 3) * 32;
            const float* src = Xb + (size_t)(kc * 64 + cl) * N + colg;
#pragma unroll
            for (int i = 0; i < 8; i++) {
                float4 v = *(const float4*)(src + i * 4);
                cvt4store(v, Bh + cl * PN + colg + i * 4, Bl + cl * PN + colg + i * 4);
            }
        }
        __syncthreads();

#pragma unroll
        for (int ks = 0; ks < 4; ks++) {
            uint32_t aH0[4], aH1[4], aL0[4], aL1[4];
            LDSM4(aH0, sb + OFF_AH + aOff + ks * 32);
            LDSM4(aH1, sb + OFF_AH + aOff + 16 * PA * 2 + ks * 32);
            LDSM4(aL0, sb + OFF_AL + aOff + ks * 32);
            LDSM4(aL1, sb + OFF_AL + aOff + 16 * PA * 2 + ks * 32);
#pragma unroll
            for (int n2 = 0; n2 < 4; n2++) {
                uint32_t bh[4], bl[4];
                LDSM4T(bh, sb + OFF_BH + bOff + ks * 16 * PN * 2 + n2 * 32);
                LDSM4T(bl, sb + OFF_BL + bOff + ks * 16 * PN * 2 + n2 * 32);
                mma16816(acc[0][n2 * 2 + 0], aH0, bh[0], bh[1]);
                mma16816(acc[0][n2 * 2 + 1], aH0, bh[2], bh[3]);
                mma16816(acc[1][n2 * 2 + 0], aH1, bh[0], bh[1]);
                mma16816(acc[1][n2 * 2 + 1], aH1, bh[2], bh[3]);
                mma16816(acc[0][n2 * 2 + 0], aH0, bl[0], bl[1]);
                mma16816(acc[0][n2 * 2 + 1], aH0, bl[2], bl[3]);
                mma16816(acc[1][n2 * 2 + 0], aH1, bl[0], bl[1]);
                mma16816(acc[1][n2 * 2 + 1], aH1, bl[2], bl[3]);
                mma16816(acc[0][n2 * 2 + 0], aL0, bh[0], bh[1]);
                mma16816(acc[0][n2 * 2 + 1], aL0, bh[2], bh[3]);
                mma16816(acc[1][n2 * 2 + 0], aL1, bh[0], bh[1]);
                mma16816(acc[1][n2 * 2 + 1], aL1, bh[2], bh[3]);
            }
        }
        __syncthreads();
    }

    const int g = lane >> 2, q = lane & 3;
    if (EPI == 2) {
        const int chBase = blockIdx.y * 64 + (wm >> 1);
#pragma unroll
        for (int mf = 0; mf < 2; mf++) {
            const int ch = chBase + mf * 8 + (g >> 1);
            float ba0 = bias[ch], bg0 = bias[C_ + ch];
            float ba1 = bias[ch + 4], bg1 = bias[C_ + ch + 4];
#pragma unroll
            for (int nb = 0; nb < 8; nb++) {
                float* d = acc[mf][nb];
                float d0 = d[0], d1 = d[1], d2 = d[2], d3 = d[3];
                if (RMS) {
                    float2 iv = *(const float2*)(inv + wn + nb * 8 + q * 2);
                    d0 *= iv.x; d1 *= iv.y; d2 *= iv.x; d3 *= iv.y;
                }
                float gt0 = __shfl_down_sync(0xffffffffu, d0, 4);
                float gt1 = __shfl_down_sync(0xffffffffu, d1, 4);
                float gt2 = __shfl_down_sync(0xffffffffu, d2, 4);
                float gt3 = __shfl_down_sync(0xffffffffu, d3, 4);
                if (!(g & 1)) {
                    float a0 = d0 + ba0, a1 = d1 + ba0;
                    float g0 = gt0 + bg0, g1 = gt1 + bg0;
                    float a2 = d2 + ba1, a3 = d3 + ba1;
                    float g2 = gt2 + bg1, g3 = gt3 + bg1;
                    float o0 = a0 * (g0 / (1.f + __expf(-g0)));
                    float o1 = a1 * (g1 / (1.f + __expf(-g1)));
                    float o2 = a2 * (g2 / (1.f + __expf(-g2)));
                    float o3 = a3 * (g3 / (1.f + __expf(-g3)));
                    int col = n0 + wn + nb * 8 + q * 2;
                    *(float2*)(Y + ((size_t)b * C_ + ch) * N + col) = make_float2(o0, o1);
                    *(float2*)(Y + ((size_t)b * C_ + ch + 4) * N + col) = make_float2(o2, o3);
                }
            }
        }
    } else {
#pragma unroll
        for (int mf = 0; mf < 2; mf++) {
            const int r0 = wm + mf * 16 + g;
            const int bi = STK ? blockIdx.y * 128 + r0 : r0;
            const float bo0 = bias[bi], bo1 = bias[bi + 8];
            float* y0 = Y + ((size_t)b * C_ + r0) * N + n0 + wn;
            float* y1 = Y + ((size_t)b * C_ + r0 + 8) * N + n0 + wn;
#pragma unroll
            for (int nb = 0; nb < 8; nb++) {
                float* d = acc[mf][nb];
                int col = nb * 8 + q * 2;
                float d0 = d[0], d1 = d[1], d2 = d[2], d3 = d[3];
                if (RMS) {
                    float2 iv = *(const float2*)(inv + wn + col);
                    d0 *= iv.x; d1 *= iv.y; d2 *= iv.x; d3 *= iv.y;
                }
                float o0 = d0 + bo0, o1 = d1 + bo0;
                float o2 = d2 + bo1, o3 = d3 + bo1;
                if (EPI == 1) {
                    o0 = o0 / (1.f + __expf(-o0));
                    o1 = o1 / (1.f + __expf(-o1));
                    o2 = o2 / (1.f + __expf(-o2));
                    o3 = o3 / (1.f + __expf(-o3));
                }
                if (EPI == 4) {
                    float2 k0 = *(const float2*)(y0 + col);
                    float2 k1 = *(const float2*)(y1 + col);
                    o0 += k0.x; o1 += k0.y;
                    o2 += k1.x; o3 += k1.y;
                }
                *(float2*)(y0 + col) = make_float2(o0, o1);
                *(float2*)(y1 + col) = make_float2(o2, o3);
            }
        }
    }
}

// ---------------- packed fp32x2 helpers (SIMT attention) ----------------
typedef unsigned long long u64;
__device__ __forceinline__ u64 pk2(float x, float y) {
    u64 r; asm("mov.b64 %0,{%1,%2};" : "=l"(r) : "f"(x), "f"(y)); return r;
}
__device__ __forceinline__ void up2(u64 v, float& x, float& y) {
    asm("mov.b64 {%0,%1},%2;" : "=f"(x), "=f"(y) : "l"(v));
}
__device__ __forceinline__ void fma2(u64& c, u64 a, u64 b) {
    asm("fma.rn.f32x2 %0,%1,%2,%0;" : "+l"(c) : "l"(a), "l"(b));
}

// ---------------- fused attention + q/o projections: one block per (b,t) ----------------
// scores = (qh^T Kq + kqb)*ss + basis^T*ps ; P = softmax_k ; out = OV@P^T + o_b + qss*qh
__global__ void __launch_bounds__(256) attn_kernel(
    const float* __restrict__ QH, const float* __restrict__ Kq, const float* __restrict__ OV,
    const float* __restrict__ Lh, const float* __restrict__ small,
    const float* __restrict__ basis, const float* __restrict__ p_ss, const float* __restrict__ p_ps,
    const float* __restrict__ p_qss, const float* __restrict__ o_b,
    float* __restrict__ Out)
{
    extern __shared__ float smf[];
    float* ks  = smf;                  // [128][64]  Kq tile
    float* vst = ks + 128 * 64;        // [64][132]  OV^T tile
    float* qs  = vst + 64 * 132;       // [128][64]  qh chunk
    float* pst = qs + 128 * 64;        // [64][68]
    float* kqs = pst + 64 * 68;        // [64] score bias per k
    const int t = blockIdx.x, b = blockIdx.y;
    const int tid = threadIdx.x;
    const int ty = tid >> 4, tx = tid & 15;
    const float ss = *p_ss, prs = *p_ps, qssv = *p_qss;

    for (int idx = tid; idx < C_ * K_; idx += 256) {
        int c = idx >> 6, kk = idx & 63;
        size_t g = (((size_t)b * C_ + c) * T_ + t) * K_ + kk;
        ks[c * 64 + kk]   = Kq[g];
        vst[kk * 132 + c] = OV[g];
    }

    // kqb[k] = ss * (w_kqb . lat_h[:,t,k] + b_kqb)   (scratch in pst before first use)
    {
        const int kk = tid & 63, cg = tid >> 6;
        float s = 0.f;
#pragma unroll 8
        for (int c = cg; c < C_; c += 4)
            s = fmaf(small[256 + c], Lh[(((size_t)b * C_ + c) * T_ + t) * K_ + kk], s);
        pst[cg * 64 + kk] = s;
        __syncthreads();
        if (tid < 64) {
            float d = pst[tid] + pst[64 + tid] + pst[128 + tid] + pst[192 + tid];
            kqs[tid] = ss * (d + small[384]);
        }
        __syncthreads();
    }

    for (int f0 = 0; f0 < F_; f0 += 64) {
        for (int idx = tid; idx < C_ * 64; idx += 256) {
            int c = idx >> 6, fl = idx & 63;
            qs[c * 64 + fl] = QH[(((size_t)b * C_ + c) * T_ + t) * F_ + f0 + fl];
        }
        __syncthreads();

        u64 acc[4][2];
#pragma unroll
        for (int r = 0; r < 4; r++) { acc[r][0] = 0ull; acc[r][1] = 0ull; }
#pragma unroll 8
        for (int c = 0; c < C_; c++) {
            float4 av = *(const float4*)&qs[c * 64 + ty * 4];
            float4 bv = *(const float4*)&ks[c * 64 + tx * 4];
            u64 b0 = pk2(bv.x, bv.y), b1 = pk2(bv.z, bv.w);
            u64 a0 = pk2(av.x, av.x); fma2(acc[0][0], a0, b0); fma2(acc[0][1], a0, b1);
            u64 a1 = pk2(av.y, av.y); fma2(acc[1][0], a1, b0); fma2(acc[1][1], a1, b1);
            u64 a2 = pk2(av.z, av.z); fma2(acc[2][0], a2, b0); fma2(acc[2][1], a2, b1);
            u64 a3 = pk2(av.w, av.w); fma2(acc[3][0], a3, b0); fma2(acc[3][1], a3, b1);
        }

#pragma unroll
        for (int r = 0; r < 4; r++) {
            float s0, s1, s2, s3;
            up2(acc[r][0], s0, s1);
            up2(acc[r][1], s2, s3);
            int f = f0 + ty * 4 + r;
            s0 = fmaf(s0, ss, kqs[tx * 4 + 0] + basis[(tx * 4 + 0) * F_ + f] * prs);
            s1 = fmaf(s1, ss, kqs[tx * 4 + 1] + basis[(tx * 4 + 1) * F_ + f] * prs);
            s2 = fmaf(s2, ss, kqs[tx * 4 + 2] + basis[(tx * 4 + 2) * F_ + f] * prs);
            s3 = fmaf(s3, ss, kqs[tx * 4 + 3] + basis[(tx * 4 + 3) * F_ + f] * prs);
            float m = fmaxf(fmaxf(s0, s1), fmaxf(s2, s3));
            m = fmaxf(m, __shfl_xor_sync(0xffffffffu, m, 1));
            m = fmaxf(m, __shfl_xor_sync(0xffffffffu, m, 2));
            m = fmaxf(m, __shfl_xor_sync(0xffffffffu, m, 4));
            m = fmaxf(m, __shfl_xor_sync(0xffffffffu, m, 8));
            float e0 = __expf(s0 - m), e1 = __expf(s1 - m);
            float e2 = __expf(s2 - m), e3 = __expf(s3 - m);
            float sum = (e0 + e1) + (e2 + e3);
            sum += __shfl_xor_sync(0xffffffffu, sum, 1);
            sum += __shfl_xor_sync(0xffffffffu, sum, 2);
            sum += __shfl_xor_sync(0xffffffffu, sum, 4);
            sum += __shfl_xor_sync(0xffffffffu, sum, 8);
            float rs = 1.f / sum;
            int fl = ty * 4 + r;
            pst[(tx * 4 + 0) * 68 + fl] = e0 * rs;
            pst[(tx * 4 + 1) * 68 + fl] = e1 * rs;
            pst[(tx * 4 + 2) * 68 + fl] = e2 * rs;
            pst[(tx * 4 + 3) * 68 + fl] = e3 * rs;
        }
        __syncthreads();

        u64 acc2[8][2];
#pragma unroll
        for (int r = 0; r < 8; r++) { acc2[r][0] = 0ull; acc2[r][1] = 0ull; }
#pragma unroll 4
        for (int kk = 0; kk < K_; kk++) {
            float4 bv = *(const float4*)&pst[kk * 68 + tx * 4];
            u64 b0 = pk2(bv.x, bv.y), b1 = pk2(bv.z, bv.w);
            const float4 v0 = *(const float4*)&vst[kk * 132 + ty * 8];
            const float4 v1 = *(const float4*)&vst[kk * 132 + ty * 8 + 4];
            const float vr[8] = {v0.x, v0.y, v0.z, v0.w, v1.x, v1.y, v1.z, v1.w};
#pragma unroll
            for (int r = 0; r < 8; r++) {
                u64 ar = pk2(vr[r], vr[r]);
                fma2(acc2[r][0], ar, b0);
                fma2(acc2[r][1], ar, b1);
            }
        }
#pragma unroll
        for (int r = 0; r < 8; r++) {
            int c = ty * 8 + r;
            const float ob = o_b[c];
            float v0, v1, v2, v3;
            up2(acc2[r][0], v0, v1);
            up2(acc2[r][1], v2, v3);
            const float* qp = &qs[c * 64 + tx * 4];
            v0 += ob + qssv * qp[0];
            v1 += ob + qssv * qp[1];
            v2 += ob + qssv * qp[2];
            v3 += ob + qssv * qp[3];
            *(float4*)&Out[(((size_t)b * C_ + c) * T_ + t) * F_ + f0 + tx * 4] =
                make_float4(v0, v1, v2, v3);
        }
        __syncthreads();
    }
}

// ---------------- launch ----------------
extern "C" void kernel_launch(void* const* d_in, const int* in_sizes, int n_in,
                              void* d_out, int out_size)
{
    const float* latent     = (const float*)d_in[0];
    const float* side       = (const float*)d_in[1];
    const float* basis      = (const float*)d_in[2];
    const float* lp_gamma   = (const float*)d_in[3];
    const float* lp_w       = (const float*)d_in[4];
    const float* lp_b       = (const float*)d_in[5];
    const float* qn_gamma   = (const float*)d_in[6];
    const float* qmlp_in_w  = (const float*)d_in[7];
    const float* qmlp_in_b  = (const float*)d_in[8];
    const float* qmlp_out_w = (const float*)d_in[9];
    const float* qmlp_out_b = (const float*)d_in[10];
    const float* q_w        = (const float*)d_in[11];
    const float* q_b        = (const float*)d_in[12];
    const float* k_w        = (const float*)d_in[13];
    const float* k_b        = (const float*)d_in[14];
    const float* v_w        = (const float*)d_in[15];
    const float* v_b        = (const float*)d_in[16];
    const float* o_w        = (const float*)d_in[17];
    const float* o_b        = (const float*)d_in[18];
    const float* ffn_gamma  = (const float*)d_in[19];
    const float* ffn_in_w   = (const float*)d_in[20];
    const float* ffn_in_b   = (const float*)d_in[21];
    const float* ffn_out_w  = (const float*)d_in[22];
    const float* ffn_out_b  = (const float*)d_in[23];
    const float* score_scale= (const float*)d_in[24];
    const float* prior_scale= (const float*)d_in[25];
    const float* qss        = (const float*)d_in[26];
    float* out = (float*)d_out;

    void* p;
    cudaGetSymbolAddress(&p, g_lat_h); float* lat_h = (float*)p;
    cudaGetSymbolAddress(&p, g_kqov);  float* kqov  = (float*)p;
    cudaGetSymbolAddress(&p, g_u);     float* u     = (float*)p;
    cudaGetSymbolAddress(&p, g_qh);    float* qh    = (float*)p;
    cudaGetSymbolAddress(&p, g_small); float* small = (float*)p;
    cudaGetSymbolAddress(&p, g_whi);   __nv_bfloat16* whi = (__nv_bfloat16*)p;
    cudaGetSymbolAddress(&p, g_wlo);   __nv_bfloat16* wlo = (__nv_bfloat16*)p;

    const size_t LSTRIDE = (size_t)B_ * C_ * NL;

    // 1 ---- weight prep + composition
    wprep_all<<<dim3(128, 8), 256>>>(lp_w, lp_gamma, qmlp_in_w, qn_gamma, qmlp_out_w,
                                     ffn_in_w, ffn_gamma, ffn_out_w,
                                     q_w, k_w, v_w, o_w, q_b, k_b, v_b, whi, wlo, small);

    cudaFuncSetAttribute(gemm_mma<0, false, false>, cudaFuncAttributeMaxDynamicSharedMemorySize, SMEM_G);
    cudaFuncSetAttribute(gemm_mma<0, false, true>,  cudaFuncAttributeMaxDynamicSharedMemorySize, SMEM_G);
    cudaFuncSetAttribute(gemm_mma<1, true, false>,  cudaFuncAttributeMaxDynamicSharedMemorySize, SMEM_G);
    cudaFuncSetAttribute(gemm_mma<2, true, false>,  cudaFuncAttributeMaxDynamicSharedMemorySize, SMEM_G);
    cudaFuncSetAttribute(gemm_mma<4, false, false>, cudaFuncAttributeMaxDynamicSharedMemorySize, SMEM_G);

    // 2 ---- latent_h = silu(lp(rmsnorm(latent)))
    gemm_mma<1, true, false><<<dim3(NL / 128, 1, B_), 256, SMEM_G>>>(
        whi + WO_LP, wlo + WO_LP, lp_b, latent, lat_h, NL, 0);
    // 3 ---- [Kq ; OV] = stacked composed projections of lat_h
    gemm_mma<0, false, true><<<dim3(NL / 128, 2, B_), 256, SMEM_G>>>(
        whi + WO_KQ, wlo + WO_KQ, small, lat_h, kqov, NL, LSTRIDE);
    // 4 ---- u = glu(qmlp_in(rmsnorm(side)))
    gemm_mma<2, true, false><<<dim3(NS / 128, 2, B_), 256, SMEM_G>>>(
        whi + WO_QMI, wlo + WO_QMI, qmlp_in_b, side, u, NS, 0);
    // 5 ---- qh = qmlp_out(u)
    gemm_mma<0, false, false><<<dim3(NS / 128, 1, B_), 256, SMEM_G>>>(
        whi + WO_QMO, wlo + WO_QMO, qmlp_out_b, u, qh, NS, 0);

    // 6 ---- fused attention (+q-proj, +o-proj, +skip) -> out
    constexpr int ATTN_SMEM = (128 * 64 + 64 * 132 + 128 * 64 + 64 * 68 + 64) * 4;
    cudaFuncSetAttribute(attn_kernel, cudaFuncAttributeMaxDynamicSharedMemorySize, ATTN_SMEM);
    attn_kernel<<<dim3(T_, B_), 256, ATTN_SMEM>>>(
        qh, kqov, kqov + LSTRIDE, lat_h, small, basis,
        score_scale, prior_scale, qss, o_b, out);

    // 7 ---- u = glu(ffn_in(rmsnorm(out)))
    gemm_mma<2, true, false><<<dim3(NS / 128, 2, B_), 256, SMEM_G>>>(
        whi + WO_FFI, wlo + WO_FFI, ffn_in_b, out, u, NS, 0);
    // 8 ---- out += ffn_out(u)
    gemm_mma<4, false, false><<<dim3(NS / 128, 1, B_), 256, SMEM_G>>>(
        whi + WO_FFO, wlo + WO_FFO, ffn_out_b, u, out, NS, 0);
}